// round 16
// baseline (speedup 1.0000x reference)
#include <cuda_runtime.h>
#include <cuda_bf16.h>
#include <cuda_fp16.h>
#include <cstdint>

#define V_SIZE 50257
#define E_SIZE 768
#define QK_SIZE 256
#define B_SIZE 4
#define T_SIZE 1024
#define M_ROWS (B_SIZE * T_SIZE)   // 4096
#define LN_EPS 1e-5f

#define BM 128
#define BN 128
#define BK 64                          // 64 fp16 = 128B rows (xor-swizzled)
#define KIT (E_SIZE / BK)              // 12 k-slices (vocab GEMM)
#define KIT_QK (QK_SIZE / BK)          // 4 k-slices (qk^T GEMM)
#define STAGES 3
#define STAGE_BYTES 32768              // A 16K | B 16K
#define SMEM_DYN (STAGES * STAGE_BYTES)  // 98304; epilogue staging (67.5K) reuses it
#define STG_STRIDE 132                 // fp32 epilogue staging stride

// ---------------- scratch (static device memory; no allocation) ----------------
__device__ __align__(256) __half g_xh[M_ROWS * E_SIZE];
__device__ __align__(256) __half g_wh[(size_t)V_SIZE * E_SIZE];
__device__ __align__(256) __half g_wqh[QK_SIZE * E_SIZE];
__device__ __align__(256) __half g_wkh[QK_SIZE * E_SIZE];
__device__ __align__(256) __half g_qh[M_ROWS * QK_SIZE];
__device__ __align__(256) __half g_kh[M_ROWS * QK_SIZE];

// ---------------- PTX helpers (generic PTX only — no sm_103a features) --------
__device__ __forceinline__ uint32_t smem_u32(const void* p) {
    uint32_t a;
    asm("{ .reg .u64 t; cvta.to.shared.u64 t, %1; cvt.u32.u64 %0, t; }" : "=r"(a) : "l"(p));
    return a;
}
__device__ __forceinline__ void cp16(uint32_t dst, const void* src) {
    asm volatile("cp.async.cg.shared.global [%0], [%1], 16;" :: "r"(dst), "l"(src));
}
#define CP_COMMIT() asm volatile("cp.async.commit_group;" ::: "memory")
#define CP_WAIT1()  asm volatile("cp.async.wait_group 1;" ::: "memory")
#define CP_WAIT0()  asm volatile("cp.async.wait_group 0;" ::: "memory")

__device__ __forceinline__ void ldsm_x4(uint32_t& r0, uint32_t& r1, uint32_t& r2, uint32_t& r3,
                                        uint32_t addr) {
    asm volatile("ldmatrix.sync.aligned.m8n8.x4.shared.b16 {%0,%1,%2,%3}, [%4];"
                 : "=r"(r0), "=r"(r1), "=r"(r2), "=r"(r3) : "r"(addr));
}
__device__ __forceinline__ void mma16816(float* d, const uint32_t* a, const uint32_t* b) {
    asm volatile("mma.sync.aligned.m16n8k16.row.col.f32.f16.f16.f32 "
                 "{%0,%1,%2,%3}, {%4,%5,%6,%7}, {%8,%9}, {%0,%1,%2,%3};"
                 : "+f"(d[0]), "+f"(d[1]), "+f"(d[2]), "+f"(d[3])
                 : "r"(a[0]), "r"(a[1]), "r"(a[2]), "r"(a[3]), "r"(b[0]), "r"(b[1]));
}
__device__ __forceinline__ uint32_t swz(int r, int c) {
    return (uint32_t)(r * 128 + ((c ^ (r & 7)) << 4));
}

// ---------------- kernel 0: gather + layernorm (fp16 x + fp32 xout) -----------
__global__ void ln_kernel(const int* __restrict__ idx,
                          const float* __restrict__ emb,
                          const float* __restrict__ gamma,
                          const float* __restrict__ beta,
                          float* __restrict__ xout) {
    int r = blockIdx.x;
    int tok = idx[r];
    const float* e = emb + (size_t)tok * E_SIZE;
    int tid = threadIdx.x;

    float v[3];
    float s = 0.f;
#pragma unroll
    for (int j = 0; j < 3; j++) { v[j] = e[tid + j * 256]; s += v[j]; }

    __shared__ float red[8];
    __shared__ float sh_mu, sh_inv;
#pragma unroll
    for (int o = 16; o > 0; o >>= 1) s += __shfl_xor_sync(0xffffffffu, s, o);
    if ((tid & 31) == 0) red[tid >> 5] = s;
    __syncthreads();
    if (tid == 0) {
        float tot = 0.f;
#pragma unroll
        for (int w = 0; w < 8; w++) tot += red[w];
        sh_mu = tot * (1.f / E_SIZE);
    }
    __syncthreads();
    float mu = sh_mu;

    float s2 = 0.f;
#pragma unroll
    for (int j = 0; j < 3; j++) { float d = v[j] - mu; s2 += d * d; }
#pragma unroll
    for (int o = 16; o > 0; o >>= 1) s2 += __shfl_xor_sync(0xffffffffu, s2, o);
    if ((tid & 31) == 0) red[tid >> 5] = s2;
    __syncthreads();
    if (tid == 0) {
        float tot = 0.f;
#pragma unroll
        for (int w = 0; w < 8; w++) tot += red[w];
        sh_inv = rsqrtf(tot * (1.f / E_SIZE) + LN_EPS);
    }
    __syncthreads();
    float inv = sh_inv;

#pragma unroll
    for (int j = 0; j < 3; j++) {
        int i = tid + j * 256;
        float y = (v[j] - mu) * inv * gamma[i] + beta[i];
        size_t o = (size_t)r * E_SIZE + i;
        g_xh[o] = __float2half_rn(y);
        if (xout) xout[o] = y;
    }
}

// ---------------- kernel 0b: head_w -> fp16 ----------------
__global__ void wsplit_kernel(const float* __restrict__ w) {
    size_t i2 = (size_t)blockIdx.x * blockDim.x + threadIdx.x;
    size_t n2 = (size_t)V_SIZE * E_SIZE / 2;
    if (i2 >= n2) return;
    float2 v = ((const float2*)w)[i2];
    ((__half2*)g_wh)[i2] = __floats2half2_rn(v.x, v.y);
}

// ---------------- kernel 0c: head_q / head_k -> fp16 ----------------
__global__ void wqk_kernel(const float* __restrict__ wq, const float* __restrict__ wk) {
    int i2 = blockIdx.x * blockDim.x + threadIdx.x;
    int n2 = QK_SIZE * E_SIZE / 2;
    if (i2 >= n2) return;
    float2 a = ((const float2*)wq)[i2];
    float2 b = ((const float2*)wk)[i2];
    ((__half2*)g_wqh)[i2] = __floats2half2_rn(a.x, a.y);
    ((__half2*)g_wkh)[i2] = __floats2half2_rn(b.x, b.y);
}

// ---------------- kernel 1: fp16 mma.sync vocab GEMM, 3-stage pipeline --------
// One __syncthreads per k-slice; loads for t+2 issued BEFORE computing slice t.
__global__ __launch_bounds__(256)
void mma_gemm_kernel(const __half* __restrict__ xh,
                     const __half* __restrict__ wh,
                     float* __restrict__ C) {
    extern __shared__ char smem[];
    const uint32_t sb = smem_u32(smem);

    const int tid = threadIdx.x;
    const int wid = tid >> 5;
    const int lane = tid & 31;
    const int m0 = blockIdx.x * BM;
    const int n0 = blockIdx.y * BN;

    const int wm = (wid & 3) * 32;
    const int wn = (wid >> 2) * 64;

    float acc[2][8][4];
#pragma unroll
    for (int mi = 0; mi < 2; mi++)
#pragma unroll
        for (int ni = 0; ni < 8; ni++)
#pragma unroll
            for (int q = 0; q < 4; q++) acc[mi][ni][q] = 0.f;

    auto load_stage = [&](int kit, int slot) {
        int kbase = kit * BK;
        uint32_t st = sb + slot * STAGE_BYTES;
        uint32_t as = st, bs = st + 16384;
#pragma unroll
        for (int j = 0; j < 4; j++) {
            int id = tid + j * 256;
            int r = id >> 3, c = id & 7;
            cp16(as + swz(r, c), xh + (size_t)(m0 + r) * E_SIZE + kbase + c * 8);
        }
#pragma unroll
        for (int j = 0; j < 4; j++) {
            int id = tid + j * 256;
            int r = id >> 3, c = id & 7;
            int gn = n0 + r;
            if (gn > V_SIZE - 1) gn = V_SIZE - 1;
            cp16(bs + swz(r, c), wh + (size_t)gn * E_SIZE + kbase + c * 8);
        }
        CP_COMMIT();
    };

    load_stage(0, 0);
    load_stage(1, 1);

    const int lrl = lane & 7;
    const int lmat = lane >> 3;

    for (int t = 0; t < KIT; t++) {
        if (t < KIT - 1) { CP_WAIT1(); } else { CP_WAIT0(); }
        __syncthreads();                       // stage t ready; slot (t+2)%3 free
        if (t + 2 < KIT) load_stage(t + 2, (t + 2) % STAGES);

        uint32_t st = sb + (t % STAGES) * STAGE_BYTES;
        uint32_t a_s = st, b_s = st + 16384;

#pragma unroll
        for (int kk = 0; kk < 4; kk++) {
            int cbase = kk * 2;
            uint32_t bfr[8][2];
#pragma unroll
            for (int pr = 0; pr < 4; pr++) {
                int r = wn + pr * 16 + lrl + (lmat >> 1) * 8;
                int c = cbase + (lmat & 1);
                uint32_t q0, q1, q2, q3;
                ldsm_x4(q0, q1, q2, q3, b_s + swz(r, c));
                bfr[pr * 2 + 0][0] = q0; bfr[pr * 2 + 0][1] = q1;
                bfr[pr * 2 + 1][0] = q2; bfr[pr * 2 + 1][1] = q3;
            }
            uint32_t afr[2][4];
#pragma unroll
            for (int mi = 0; mi < 2; mi++) {
                int r = wm + mi * 16 + lrl + (lmat & 1) * 8;
                int c = cbase + (lmat >> 1);
                ldsm_x4(afr[mi][0], afr[mi][1], afr[mi][2], afr[mi][3], a_s + swz(r, c));
            }
#pragma unroll
            for (int mi = 0; mi < 2; mi++)
#pragma unroll
                for (int ni = 0; ni < 8; ni++)
                    mma16816(acc[mi][ni], afr[mi], bfr[ni]);
        }
    }

    // ---- staged epilogue: fragments -> SMEM -> coalesced global stores ----
    __syncthreads();                       // pipeline buffers now reusable
    float* stg = (float*)smem;             // 128 x STG_STRIDE fp32
    const int lr = lane >> 2;
    const int lc = (lane & 3) * 2;
#pragma unroll
    for (int mi = 0; mi < 2; mi++) {
        int r0 = wm + mi * 16 + lr;
#pragma unroll
        for (int ni = 0; ni < 8; ni++) {
            int c0 = wn + ni * 8 + lc;
            stg[r0 * STG_STRIDE + c0]           = acc[mi][ni][0];
            stg[r0 * STG_STRIDE + c0 + 1]       = acc[mi][ni][1];
            stg[(r0 + 8) * STG_STRIDE + c0]     = acc[mi][ni][2];
            stg[(r0 + 8) * STG_STRIDE + c0 + 1] = acc[mi][ni][3];
        }
    }
    __syncthreads();
#pragma unroll
    for (int i = 0; i < 64; i++) {
        int e = tid + i * 256;             // 0..16383
        int r = e >> 7, c = e & 127;       // consecutive lanes -> consecutive c
        int col = n0 + c;
        if (col < V_SIZE)
            C[(size_t)(m0 + r) * V_SIZE + col] = stg[r * STG_STRIDE + c];
    }
}

// ---------------- kernel 2: fp16 q+k projections (3-stage, z selects) ---------
__global__ __launch_bounds__(256)
void qkproj_kernel(const __half* __restrict__ xh) {
    extern __shared__ char smem[];
    const uint32_t sb = smem_u32(smem);

    const __half* W = blockIdx.z ? g_wkh : g_wqh;
    __half* O = blockIdx.z ? g_kh : g_qh;

    const int tid = threadIdx.x;
    const int wid = tid >> 5;
    const int lane = tid & 31;
    const int m0 = blockIdx.x * BM;
    const int n0 = blockIdx.y * BN;

    const int wm = (wid & 3) * 32;
    const int wn = (wid >> 2) * 64;

    float acc[2][8][4];
#pragma unroll
    for (int mi = 0; mi < 2; mi++)
#pragma unroll
        for (int ni = 0; ni < 8; ni++)
#pragma unroll
            for (int q = 0; q < 4; q++) acc[mi][ni][q] = 0.f;

    auto load_stage = [&](int kit, int slot) {
        int kbase = kit * BK;
        uint32_t st = sb + slot * STAGE_BYTES;
        uint32_t as = st, bs = st + 16384;
#pragma unroll
        for (int j = 0; j < 4; j++) {
            int id = tid + j * 256;
            int r = id >> 3, c = id & 7;
            cp16(as + swz(r, c), xh + (size_t)(m0 + r) * E_SIZE + kbase + c * 8);
        }
#pragma unroll
        for (int j = 0; j < 4; j++) {
            int id = tid + j * 256;
            int r = id >> 3, c = id & 7;
            cp16(bs + swz(r, c), W + (size_t)(n0 + r) * E_SIZE + kbase + c * 8);
        }
        CP_COMMIT();
    };

    load_stage(0, 0);
    load_stage(1, 1);

    const int lrl = lane & 7;
    const int lmat = lane >> 3;

    for (int t = 0; t < KIT; t++) {
        if (t < KIT - 1) { CP_WAIT1(); } else { CP_WAIT0(); }
        __syncthreads();
        if (t + 2 < KIT) load_stage(t + 2, (t + 2) % STAGES);

        uint32_t st = sb + (t % STAGES) * STAGE_BYTES;
        uint32_t a_s = st, b_s = st + 16384;

#pragma unroll
        for (int kk = 0; kk < 4; kk++) {
            int cbase = kk * 2;
            uint32_t bfr[8][2];
#pragma unroll
            for (int pr = 0; pr < 4; pr++) {
                int r = wn + pr * 16 + lrl + (lmat >> 1) * 8;
                int c = cbase + (lmat & 1);
                uint32_t q0, q1, q2, q3;
                ldsm_x4(q0, q1, q2, q3, b_s + swz(r, c));
                bfr[pr * 2 + 0][0] = q0; bfr[pr * 2 + 0][1] = q1;
                bfr[pr * 2 + 1][0] = q2; bfr[pr * 2 + 1][1] = q3;
            }
            uint32_t afr[2][4];
#pragma unroll
            for (int mi = 0; mi < 2; mi++) {
                int r = wm + mi * 16 + lrl + (lmat & 1) * 8;
                int c = cbase + (lmat >> 1);
                ldsm_x4(afr[mi][0], afr[mi][1], afr[mi][2], afr[mi][3], a_s + swz(r, c));
            }
#pragma unroll
            for (int mi = 0; mi < 2; mi++)
#pragma unroll
                for (int ni = 0; ni < 8; ni++)
                    mma16816(acc[mi][ni], afr[mi], bfr[ni]);
        }
    }

    const int lr = lane >> 2;
    const int lc = (lane & 3) * 2;
#pragma unroll
    for (int mi = 0; mi < 2; mi++) {
        int row0 = m0 + wm + mi * 16 + lr;
#pragma unroll
        for (int ni = 0; ni < 8; ni++) {
            int col = n0 + wn + ni * 8 + lc;
            *(__half2*)(O + (size_t)row0 * QK_SIZE + col) =
                __floats2half2_rn(acc[mi][ni][0], acc[mi][ni][1]);
            *(__half2*)(O + (size_t)(row0 + 8) * QK_SIZE + col) =
                __floats2half2_rn(acc[mi][ni][2], acc[mi][ni][3]);
        }
    }
}

// ---------------- kernel 3: fused c = q k^T / QK + scatter-add into logits ----
__global__ __launch_bounds__(256)
void qk_scatter_kernel(const int* __restrict__ idx, float* __restrict__ logits) {
    extern __shared__ char smem[];
    const uint32_t sb = smem_u32(smem);
    __shared__ int ibs[128];

    int bx = blockIdx.x;
    int b = bx / 36;
    int p = bx % 36;
    int mt = 0;
    while ((mt + 1) * (mt + 2) / 2 <= p) mt++;
    int nt = p - mt * (mt + 1) / 2;

    const int tid = threadIdx.x;
    const int wid = tid >> 5;
    const int lane = tid & 31;
    const int m0 = b * T_SIZE + mt * 128;
    const int n0 = b * T_SIZE + nt * 128;

    if (tid < 128) ibs[tid] = idx[n0 + tid];

    const int wm = (wid & 3) * 32;
    const int wn = (wid >> 2) * 64;

    float acc[2][8][4];
#pragma unroll
    for (int mi = 0; mi < 2; mi++)
#pragma unroll
        for (int ni = 0; ni < 8; ni++)
#pragma unroll
            for (int q = 0; q < 4; q++) acc[mi][ni][q] = 0.f;

    auto load_stage = [&](int kit, int slot) {
        int kbase = kit * BK;
        uint32_t st = sb + slot * STAGE_BYTES;
        uint32_t as = st, bs = st + 16384;
#pragma unroll
        for (int j = 0; j < 4; j++) {
            int id = tid + j * 256;
            int r = id >> 3, c = id & 7;
            cp16(as + swz(r, c), g_qh + (size_t)(m0 + r) * QK_SIZE + kbase + c * 8);
        }
#pragma unroll
        for (int j = 0; j < 4; j++) {
            int id = tid + j * 256;
            int r = id >> 3, c = id & 7;
            cp16(bs + swz(r, c), g_kh + (size_t)(n0 + r) * QK_SIZE + kbase + c * 8);
        }
        CP_COMMIT();
    };

    load_stage(0, 0);
    load_stage(1, 1);

    const int lrl = lane & 7;
    const int lmat = lane >> 3;

    for (int t = 0; t < KIT_QK; t++) {
        if (t < KIT_QK - 1) { CP_WAIT1(); } else { CP_WAIT0(); }
        __syncthreads();
        if (t + 2 < KIT_QK) load_stage(t + 2, (t + 2) % STAGES);

        uint32_t st = sb + (t % STAGES) * STAGE_BYTES;
        uint32_t a_s = st, b_s = st + 16384;

#pragma unroll
        for (int kk = 0; kk < 4; kk++) {
            int cbase = kk * 2;
            uint32_t bfr[8][2];
#pragma unroll
            for (int pr = 0; pr < 4; pr++) {
                int r = wn + pr * 16 + lrl + (lmat >> 1) * 8;
                int c = cbase + (lmat & 1);
                uint32_t q0, q1, q2, q3;
                ldsm_x4(q0, q1, q2, q3, b_s + swz(r, c));
                bfr[pr * 2 + 0][0] = q0; bfr[pr * 2 + 0][1] = q1;
                bfr[pr * 2 + 1][0] = q2; bfr[pr * 2 + 1][1] = q3;
            }
            uint32_t afr[2][4];
#pragma unroll
            for (int mi = 0; mi < 2; mi++) {
                int r = wm + mi * 16 + lrl + (lmat & 1) * 8;
                int c = cbase + (lmat >> 1);
                ldsm_x4(afr[mi][0], afr[mi][1], afr[mi][2], afr[mi][3], a_s + swz(r, c));
            }
#pragma unroll
            for (int mi = 0; mi < 2; mi++)
#pragma unroll
                for (int ni = 0; ni < 8; ni++)
                    mma16816(acc[mi][ni], afr[mi], bfr[ni]);
        }
    }

    const int lr = lane >> 2;
    const int lc = (lane & 3) * 2;
    const float sc = 1.0f / QK_SIZE;
#pragma unroll
    for (int mi = 0; mi < 2; mi++) {
        int tl0 = mt * 128 + wm + mi * 16 + lr;
#pragma unroll
        for (int ni = 0; ni < 8; ni++) {
            int cl = wn + ni * 8 + lc;
            int sl = nt * 128 + cl;
            float* l0 = logits + (size_t)(b * T_SIZE + tl0) * V_SIZE;
            float* l1 = logits + (size_t)(b * T_SIZE + tl0 + 8) * V_SIZE;
            int v0 = ibs[cl], v1 = ibs[cl + 1];
            if (sl <= tl0)         atomicAdd(l0 + v0, acc[mi][ni][0] * sc);
            if (sl + 1 <= tl0)     atomicAdd(l0 + v1, acc[mi][ni][1] * sc);
            if (sl <= tl0 + 8)     atomicAdd(l1 + v0, acc[mi][ni][2] * sc);
            if (sl + 1 <= tl0 + 8) atomicAdd(l1 + v1, acc[mi][ni][3] * sc);
        }
    }
}

// ---------------- launch ----------------
extern "C" void kernel_launch(void* const* d_in, const int* in_sizes, int n_in,
                              void* d_out, int out_size) {
    const int*   idx    = (const int*)d_in[0];
    const float* emb_w  = (const float*)d_in[1];
    const float* ln_g   = (const float*)d_in[2];
    const float* ln_b   = (const float*)d_in[3];
    const float* head_w = (const float*)d_in[4];
    const float* head_q = (const float*)d_in[5];
    const float* head_k = (const float*)d_in[6];

    void *pxh, *pwh;
    cudaGetSymbolAddress(&pxh, g_xh);
    cudaGetSymbolAddress(&pwh, g_wh);

    float* out    = (float*)d_out;
    float* logits = out;

    const size_t logits_elems = (size_t)M_ROWS * V_SIZE;
    const size_t x_elems      = (size_t)M_ROWS * E_SIZE;
    float* xout = nullptr;
    if ((size_t)out_size >= logits_elems + x_elems)
        xout = out + ((size_t)out_size - x_elems);

    // 1) x = layernorm(emb[idx]) (fp16 x + fp32 xout)
    ln_kernel<<<M_ROWS, 256>>>(idx, emb_w, ln_g, ln_b, xout);

    // 1b) head_w -> fp16 ; head_q/head_k -> fp16
    {
        size_t n2 = (size_t)V_SIZE * E_SIZE / 2;
        wsplit_kernel<<<(unsigned)((n2 + 255) / 256), 256>>>(head_w);
        int m2 = QK_SIZE * E_SIZE / 2;
        wqk_kernel<<<(m2 + 255) / 256, 256>>>(head_q, head_k);
    }

    // 2) q,k projections via fp16 mma.sync (outputs fp16)
    {
        cudaFuncSetAttribute(qkproj_kernel, cudaFuncAttributeMaxDynamicSharedMemorySize, SMEM_DYN);
        dim3 grid(M_ROWS / BM, QK_SIZE / BN, 2);
        qkproj_kernel<<<grid, 256, SMEM_DYN>>>((const __half*)pxh);
    }

    // 3) logits = x @ head_w^T via single-pass fp16 mma.sync (3-stage)
    {
        cudaFuncSetAttribute(mma_gemm_kernel, cudaFuncAttributeMaxDynamicSharedMemorySize, SMEM_DYN);
        dim3 grid(M_ROWS / BM, (V_SIZE + BN - 1) / BN);
        mma_gemm_kernel<<<grid, 256, SMEM_DYN>>>(
            (const __half*)pxh, (const __half*)pwh, logits);
    }

    // 4) fused causal qk^T + copy-scatter into logits
    {
        cudaFuncSetAttribute(qk_scatter_kernel, cudaFuncAttributeMaxDynamicSharedMemorySize, SMEM_DYN);
        qk_scatter_kernel<<<B_SIZE * 36, 256, SMEM_DYN>>>(idx, logits);
    }
}

// round 17
// speedup vs baseline: 1.0366x; 1.0366x over previous
#include <cuda_runtime.h>
#include <cuda_bf16.h>
#include <cuda_fp16.h>
#include <cstdint>

#define V_SIZE 50257
#define E_SIZE 768
#define QK_SIZE 256
#define B_SIZE 4
#define T_SIZE 1024
#define M_ROWS (B_SIZE * T_SIZE)   // 4096
#define LN_EPS 1e-5f

#define BM 128
#define BN 128
#define BK 64                          // 64 fp16 = 128B rows (xor-swizzled)
#define KIT (E_SIZE / BK)              // 12 k-slices (vocab GEMM)
#define KIT_QK (QK_SIZE / BK)          // 4 k-slices (qk^T GEMM)
#define STAGE_BYTES 32768              // A 16K | B 16K
#define STG_STRIDE 132                 // fp32 epilogue staging stride
#define SMEM_DYN (128 * STG_STRIDE * 4)  // 67584 > 2*STAGE_BYTES, covers both uses

// ---------------- scratch (static device memory; no allocation) ----------------
__device__ __align__(256) __half g_xh[M_ROWS * E_SIZE];
__device__ __align__(256) __half g_wh[(size_t)V_SIZE * E_SIZE];
__device__ __align__(256) __half g_wqh[QK_SIZE * E_SIZE];
__device__ __align__(256) __half g_wkh[QK_SIZE * E_SIZE];
__device__ __align__(256) __half g_qh[M_ROWS * QK_SIZE];
__device__ __align__(256) __half g_kh[M_ROWS * QK_SIZE];

// ---------------- PTX helpers (generic PTX only — no sm_103a features) --------
__device__ __forceinline__ uint32_t smem_u32(const void* p) {
    uint32_t a;
    asm("{ .reg .u64 t; cvta.to.shared.u64 t, %1; cvt.u32.u64 %0, t; }" : "=r"(a) : "l"(p));
    return a;
}
__device__ __forceinline__ void cp16(uint32_t dst, const void* src) {
    asm volatile("cp.async.cg.shared.global [%0], [%1], 16;" :: "r"(dst), "l"(src));
}
#define CP_COMMIT() asm volatile("cp.async.commit_group;" ::: "memory")
#define CP_WAIT1()  asm volatile("cp.async.wait_group 1;" ::: "memory")
#define CP_WAIT0()  asm volatile("cp.async.wait_group 0;" ::: "memory")

__device__ __forceinline__ void ldsm_x4(uint32_t& r0, uint32_t& r1, uint32_t& r2, uint32_t& r3,
                                        uint32_t addr) {
    asm volatile("ldmatrix.sync.aligned.m8n8.x4.shared.b16 {%0,%1,%2,%3}, [%4];"
                 : "=r"(r0), "=r"(r1), "=r"(r2), "=r"(r3) : "r"(addr));
}
__device__ __forceinline__ void mma16816(float* d, const uint32_t* a, const uint32_t* b) {
    asm volatile("mma.sync.aligned.m16n8k16.row.col.f32.f16.f16.f32 "
                 "{%0,%1,%2,%3}, {%4,%5,%6,%7}, {%8,%9}, {%0,%1,%2,%3};"
                 : "+f"(d[0]), "+f"(d[1]), "+f"(d[2]), "+f"(d[3])
                 : "r"(a[0]), "r"(a[1]), "r"(a[2]), "r"(a[3]), "r"(b[0]), "r"(b[1]));
}
__device__ __forceinline__ uint32_t swz(int r, int c) {
    return (uint32_t)(r * 128 + ((c ^ (r & 7)) << 4));
}

// ---------------- kernel 0: gather + layernorm (fp16 x + fp32 xout) -----------
__global__ void ln_kernel(const int* __restrict__ idx,
                          const float* __restrict__ emb,
                          const float* __restrict__ gamma,
                          const float* __restrict__ beta,
                          float* __restrict__ xout) {
    int r = blockIdx.x;
    int tok = idx[r];
    const float* e = emb + (size_t)tok * E_SIZE;
    int tid = threadIdx.x;

    float v[3];
    float s = 0.f;
#pragma unroll
    for (int j = 0; j < 3; j++) { v[j] = e[tid + j * 256]; s += v[j]; }

    __shared__ float red[8];
    __shared__ float sh_mu, sh_inv;
#pragma unroll
    for (int o = 16; o > 0; o >>= 1) s += __shfl_xor_sync(0xffffffffu, s, o);
    if ((tid & 31) == 0) red[tid >> 5] = s;
    __syncthreads();
    if (tid == 0) {
        float tot = 0.f;
#pragma unroll
        for (int w = 0; w < 8; w++) tot += red[w];
        sh_mu = tot * (1.f / E_SIZE);
    }
    __syncthreads();
    float mu = sh_mu;

    float s2 = 0.f;
#pragma unroll
    for (int j = 0; j < 3; j++) { float d = v[j] - mu; s2 += d * d; }
#pragma unroll
    for (int o = 16; o > 0; o >>= 1) s2 += __shfl_xor_sync(0xffffffffu, s2, o);
    if ((tid & 31) == 0) red[tid >> 5] = s2;
    __syncthreads();
    if (tid == 0) {
        float tot = 0.f;
#pragma unroll
        for (int w = 0; w < 8; w++) tot += red[w];
        sh_inv = rsqrtf(tot * (1.f / E_SIZE) + LN_EPS);
    }
    __syncthreads();
    float inv = sh_inv;

#pragma unroll
    for (int j = 0; j < 3; j++) {
        int i = tid + j * 256;
        float y = (v[j] - mu) * inv * gamma[i] + beta[i];
        size_t o = (size_t)r * E_SIZE + i;
        g_xh[o] = __float2half_rn(y);
        if (xout) xout[o] = y;
    }
}

// ---------------- kernel 0b: head_w / head_q / head_k -> fp16 (merged) --------
__global__ void wconv_kernel(const float* __restrict__ w,
                             const float* __restrict__ wq,
                             const float* __restrict__ wk) {
    size_t i2 = (size_t)blockIdx.x * blockDim.x + threadIdx.x;
    const size_t n2 = (size_t)V_SIZE * E_SIZE / 2;
    const size_t m2 = (size_t)QK_SIZE * E_SIZE / 2;
    if (i2 < n2) {
        float2 v = ((const float2*)w)[i2];
        ((__half2*)g_wh)[i2] = __floats2half2_rn(v.x, v.y);
    }
    if (i2 < m2) {
        float2 a = ((const float2*)wq)[i2];
        float2 b = ((const float2*)wk)[i2];
        ((__half2*)g_wqh)[i2] = __floats2half2_rn(a.x, a.y);
        ((__half2*)g_wkh)[i2] = __floats2half2_rn(b.x, b.y);
    }
}

// ---------------- kernel 1: fp16 mma.sync vocab GEMM (2-stage, R14 form) ------
__global__ __launch_bounds__(256)
void mma_gemm_kernel(const __half* __restrict__ xh,
                     const __half* __restrict__ wh,
                     float* __restrict__ C) {
    extern __shared__ char smem[];
    const uint32_t sb = smem_u32(smem);

    const int tid = threadIdx.x;
    const int wid = tid >> 5;
    const int lane = tid & 31;
    const int m0 = blockIdx.x * BM;
    const int n0 = blockIdx.y * BN;

    const int wm = (wid & 3) * 32;
    const int wn = (wid >> 2) * 64;

    float acc[2][8][4];
#pragma unroll
    for (int mi = 0; mi < 2; mi++)
#pragma unroll
        for (int ni = 0; ni < 8; ni++)
#pragma unroll
            for (int q = 0; q < 4; q++) acc[mi][ni][q] = 0.f;

    auto load_stage = [&](int kit, int slot) {
        int kbase = kit * BK;
        uint32_t st = sb + slot * STAGE_BYTES;
        uint32_t as = st, bs = st + 16384;
#pragma unroll
        for (int j = 0; j < 4; j++) {
            int id = tid + j * 256;
            int r = id >> 3, c = id & 7;
            cp16(as + swz(r, c), xh + (size_t)(m0 + r) * E_SIZE + kbase + c * 8);
        }
#pragma unroll
        for (int j = 0; j < 4; j++) {
            int id = tid + j * 256;
            int r = id >> 3, c = id & 7;
            int gn = n0 + r;
            if (gn > V_SIZE - 1) gn = V_SIZE - 1;
            cp16(bs + swz(r, c), wh + (size_t)gn * E_SIZE + kbase + c * 8);
        }
        CP_COMMIT();
    };

    load_stage(0, 0);
    load_stage(1, 1);

    const int lrl = lane & 7;
    const int lmat = lane >> 3;

    for (int t = 0; t < KIT; t++) {
        if (t < KIT - 2) { CP_WAIT1(); } else { CP_WAIT0(); }
        __syncthreads();
        uint32_t st = sb + (t & 1) * STAGE_BYTES;
        uint32_t a_s = st, b_s = st + 16384;

#pragma unroll
        for (int kk = 0; kk < 4; kk++) {
            int cbase = kk * 2;
            uint32_t bfr[8][2];
#pragma unroll
            for (int pr = 0; pr < 4; pr++) {
                int r = wn + pr * 16 + lrl + (lmat >> 1) * 8;
                int c = cbase + (lmat & 1);
                uint32_t q0, q1, q2, q3;
                ldsm_x4(q0, q1, q2, q3, b_s + swz(r, c));
                bfr[pr * 2 + 0][0] = q0; bfr[pr * 2 + 0][1] = q1;
                bfr[pr * 2 + 1][0] = q2; bfr[pr * 2 + 1][1] = q3;
            }
            uint32_t afr[2][4];
#pragma unroll
            for (int mi = 0; mi < 2; mi++) {
                int r = wm + mi * 16 + lrl + (lmat & 1) * 8;
                int c = cbase + (lmat >> 1);
                ldsm_x4(afr[mi][0], afr[mi][1], afr[mi][2], afr[mi][3], a_s + swz(r, c));
            }
#pragma unroll
            for (int mi = 0; mi < 2; mi++)
#pragma unroll
                for (int ni = 0; ni < 8; ni++)
                    mma16816(acc[mi][ni], afr[mi], bfr[ni]);
        }
        __syncthreads();
        if (t + 2 < KIT) load_stage(t + 2, t & 1);
    }

    // ---- staged epilogue: fragments -> SMEM -> coalesced global stores ----
    __syncthreads();
    float* stg = (float*)smem;
    const int lr = lane >> 2;
    const int lc = (lane & 3) * 2;
#pragma unroll
    for (int mi = 0; mi < 2; mi++) {
        int r0 = wm + mi * 16 + lr;
#pragma unroll
        for (int ni = 0; ni < 8; ni++) {
            int c0 = wn + ni * 8 + lc;
            stg[r0 * STG_STRIDE + c0]           = acc[mi][ni][0];
            stg[r0 * STG_STRIDE + c0 + 1]       = acc[mi][ni][1];
            stg[(r0 + 8) * STG_STRIDE + c0]     = acc[mi][ni][2];
            stg[(r0 + 8) * STG_STRIDE + c0 + 1] = acc[mi][ni][3];
        }
    }
    __syncthreads();
#pragma unroll
    for (int i = 0; i < 64; i++) {
        int e = tid + i * 256;
        int r = e >> 7, c = e & 127;
        int col = n0 + c;
        if (col < V_SIZE)
            C[(size_t)(m0 + r) * V_SIZE + col] = stg[r * STG_STRIDE + c];
    }
}

// ---------------- kernel 2: fp16 q+k projections (2-stage, z selects) ---------
__global__ __launch_bounds__(256)
void qkproj_kernel(const __half* __restrict__ xh) {
    extern __shared__ char smem[];
    const uint32_t sb = smem_u32(smem);

    const __half* W = blockIdx.z ? g_wkh : g_wqh;
    __half* O = blockIdx.z ? g_kh : g_qh;

    const int tid = threadIdx.x;
    const int wid = tid >> 5;
    const int lane = tid & 31;
    const int m0 = blockIdx.x * BM;
    const int n0 = blockIdx.y * BN;

    const int wm = (wid & 3) * 32;
    const int wn = (wid >> 2) * 64;

    float acc[2][8][4];
#pragma unroll
    for (int mi = 0; mi < 2; mi++)
#pragma unroll
        for (int ni = 0; ni < 8; ni++)
#pragma unroll
            for (int q = 0; q < 4; q++) acc[mi][ni][q] = 0.f;

    auto load_stage = [&](int kit, int slot) {
        int kbase = kit * BK;
        uint32_t st = sb + slot * STAGE_BYTES;
        uint32_t as = st, bs = st + 16384;
#pragma unroll
        for (int j = 0; j < 4; j++) {
            int id = tid + j * 256;
            int r = id >> 3, c = id & 7;
            cp16(as + swz(r, c), xh + (size_t)(m0 + r) * E_SIZE + kbase + c * 8);
        }
#pragma unroll
        for (int j = 0; j < 4; j++) {
            int id = tid + j * 256;
            int r = id >> 3, c = id & 7;
            cp16(bs + swz(r, c), W + (size_t)(n0 + r) * E_SIZE + kbase + c * 8);
        }
        CP_COMMIT();
    };

    load_stage(0, 0);
    load_stage(1, 1);

    const int lrl = lane & 7;
    const int lmat = lane >> 3;

    for (int t = 0; t < KIT; t++) {
        if (t < KIT - 2) { CP_WAIT1(); } else { CP_WAIT0(); }
        __syncthreads();
        uint32_t st = sb + (t & 1) * STAGE_BYTES;
        uint32_t a_s = st, b_s = st + 16384;

#pragma unroll
        for (int kk = 0; kk < 4; kk++) {
            int cbase = kk * 2;
            uint32_t bfr[8][2];
#pragma unroll
            for (int pr = 0; pr < 4; pr++) {
                int r = wn + pr * 16 + lrl + (lmat >> 1) * 8;
                int c = cbase + (lmat & 1);
                uint32_t q0, q1, q2, q3;
                ldsm_x4(q0, q1, q2, q3, b_s + swz(r, c));
                bfr[pr * 2 + 0][0] = q0; bfr[pr * 2 + 0][1] = q1;
                bfr[pr * 2 + 1][0] = q2; bfr[pr * 2 + 1][1] = q3;
            }
            uint32_t afr[2][4];
#pragma unroll
            for (int mi = 0; mi < 2; mi++) {
                int r = wm + mi * 16 + lrl + (lmat & 1) * 8;
                int c = cbase + (lmat >> 1);
                ldsm_x4(afr[mi][0], afr[mi][1], afr[mi][2], afr[mi][3], a_s + swz(r, c));
            }
#pragma unroll
            for (int mi = 0; mi < 2; mi++)
#pragma unroll
                for (int ni = 0; ni < 8; ni++)
                    mma16816(acc[mi][ni], afr[mi], bfr[ni]);
        }
        __syncthreads();
        if (t + 2 < KIT) load_stage(t + 2, t & 1);
    }

    const int lr = lane >> 2;
    const int lc = (lane & 3) * 2;
#pragma unroll
    for (int mi = 0; mi < 2; mi++) {
        int row0 = m0 + wm + mi * 16 + lr;
#pragma unroll
        for (int ni = 0; ni < 8; ni++) {
            int col = n0 + wn + ni * 8 + lc;
            *(__half2*)(O + (size_t)row0 * QK_SIZE + col) =
                __floats2half2_rn(acc[mi][ni][0], acc[mi][ni][1]);
            *(__half2*)(O + (size_t)(row0 + 8) * QK_SIZE + col) =
                __floats2half2_rn(acc[mi][ni][2], acc[mi][ni][3]);
        }
    }
}

// ---------------- kernel 3: fused c = q k^T / QK + scatter-add into logits ----
__global__ __launch_bounds__(256)
void qk_scatter_kernel(const int* __restrict__ idx, float* __restrict__ logits) {
    extern __shared__ char smem[];
    const uint32_t sb = smem_u32(smem);
    __shared__ int ibs[128];

    int bx = blockIdx.x;
    int b = bx / 36;
    int p = bx % 36;
    int mt = 0;
    while ((mt + 1) * (mt + 2) / 2 <= p) mt++;
    int nt = p - mt * (mt + 1) / 2;

    const int tid = threadIdx.x;
    const int wid = tid >> 5;
    const int lane = tid & 31;
    const int m0 = b * T_SIZE + mt * 128;
    const int n0 = b * T_SIZE + nt * 128;

    if (tid < 128) ibs[tid] = __ldg(idx + n0 + tid);

    const int wm = (wid & 3) * 32;
    const int wn = (wid >> 2) * 64;

    float acc[2][8][4];
#pragma unroll
    for (int mi = 0; mi < 2; mi++)
#pragma unroll
        for (int ni = 0; ni < 8; ni++)
#pragma unroll
            for (int q = 0; q < 4; q++) acc[mi][ni][q] = 0.f;

    auto load_stage = [&](int kit, int slot) {
        int kbase = kit * BK;
        uint32_t st = sb + slot * STAGE_BYTES;
        uint32_t as = st, bs = st + 16384;
#pragma unroll
        for (int j = 0; j < 4; j++) {
            int id = tid + j * 256;
            int r = id >> 3, c = id & 7;
            cp16(as + swz(r, c), g_qh + (size_t)(m0 + r) * QK_SIZE + kbase + c * 8);
        }
#pragma unroll
        for (int j = 0; j < 4; j++) {
            int id = tid + j * 256;
            int r = id >> 3, c = id & 7;
            cp16(bs + swz(r, c), g_kh + (size_t)(n0 + r) * QK_SIZE + kbase + c * 8);
        }
        CP_COMMIT();
    };

    load_stage(0, 0);
    load_stage(1, 1);

    const int lrl = lane & 7;
    const int lmat = lane >> 3;

    for (int t = 0; t < KIT_QK; t++) {
        if (t < KIT_QK - 2) { CP_WAIT1(); } else { CP_WAIT0(); }
        __syncthreads();
        uint32_t st = sb + (t & 1) * STAGE_BYTES;
        uint32_t a_s = st, b_s = st + 16384;

#pragma unroll
        for (int kk = 0; kk < 4; kk++) {
            int cbase = kk * 2;
            uint32_t bfr[8][2];
#pragma unroll
            for (int pr = 0; pr < 4; pr++) {
                int r = wn + pr * 16 + lrl + (lmat >> 1) * 8;
                int c = cbase + (lmat & 1);
                uint32_t q0, q1, q2, q3;
                ldsm_x4(q0, q1, q2, q3, b_s + swz(r, c));
                bfr[pr * 2 + 0][0] = q0; bfr[pr * 2 + 0][1] = q1;
                bfr[pr * 2 + 1][0] = q2; bfr[pr * 2 + 1][1] = q3;
            }
            uint32_t afr[2][4];
#pragma unroll
            for (int mi = 0; mi < 2; mi++) {
                int r = wm + mi * 16 + lrl + (lmat & 1) * 8;
                int c = cbase + (lmat >> 1);
                ldsm_x4(afr[mi][0], afr[mi][1], afr[mi][2], afr[mi][3], a_s + swz(r, c));
            }
#pragma unroll
            for (int mi = 0; mi < 2; mi++)
#pragma unroll
                for (int ni = 0; ni < 8; ni++)
                    mma16816(acc[mi][ni], afr[mi], bfr[ni]);
        }
        __syncthreads();
        if (t + 2 < KIT_QK) load_stage(t + 2, t & 1);
    }

    const int lr = lane >> 2;
    const int lc = (lane & 3) * 2;
    const float sc = 1.0f / QK_SIZE;
#pragma unroll
    for (int mi = 0; mi < 2; mi++) {
        int tl0 = mt * 128 + wm + mi * 16 + lr;
#pragma unroll
        for (int ni = 0; ni < 8; ni++) {
            int cl = wn + ni * 8 + lc;
            int sl = nt * 128 + cl;
            float* l0 = logits + (size_t)(b * T_SIZE + tl0) * V_SIZE;
            float* l1 = logits + (size_t)(b * T_SIZE + tl0 + 8) * V_SIZE;
            int v0 = ibs[cl], v1 = ibs[cl + 1];
            if (sl <= tl0)         atomicAdd(l0 + v0, acc[mi][ni][0] * sc);
            if (sl + 1 <= tl0)     atomicAdd(l0 + v1, acc[mi][ni][1] * sc);
            if (sl <= tl0 + 8)     atomicAdd(l1 + v0, acc[mi][ni][2] * sc);
            if (sl + 1 <= tl0 + 8) atomicAdd(l1 + v1, acc[mi][ni][3] * sc);
        }
    }
}

// ---------------- launch ----------------
extern "C" void kernel_launch(void* const* d_in, const int* in_sizes, int n_in,
                              void* d_out, int out_size) {
    const int*   idx    = (const int*)d_in[0];
    const float* emb_w  = (const float*)d_in[1];
    const float* ln_g   = (const float*)d_in[2];
    const float* ln_b   = (const float*)d_in[3];
    const float* head_w = (const float*)d_in[4];
    const float* head_q = (const float*)d_in[5];
    const float* head_k = (const float*)d_in[6];

    void *pxh, *pwh;
    cudaGetSymbolAddress(&pxh, g_xh);
    cudaGetSymbolAddress(&pwh, g_wh);

    float* out    = (float*)d_out;
    float* logits = out;

    const size_t logits_elems = (size_t)M_ROWS * V_SIZE;
    const size_t x_elems      = (size_t)M_ROWS * E_SIZE;
    float* xout = nullptr;
    if ((size_t)out_size >= logits_elems + x_elems)
        xout = out + ((size_t)out_size - x_elems);

    // 1) x = layernorm(emb[idx]) (fp16 x + fp32 xout)
    ln_kernel<<<M_ROWS, 256>>>(idx, emb_w, ln_g, ln_b, xout);

    // 1b) all weights -> fp16 in one merged launch
    {
        size_t n2 = (size_t)V_SIZE * E_SIZE / 2;
        wconv_kernel<<<(unsigned)((n2 + 255) / 256), 256>>>(head_w, head_q, head_k);
    }

    // 2) q,k projections via fp16 mma.sync (outputs fp16)
    {
        cudaFuncSetAttribute(qkproj_kernel, cudaFuncAttributeMaxDynamicSharedMemorySize, SMEM_DYN);
        dim3 grid(M_ROWS / BM, QK_SIZE / BN, 2);
        qkproj_kernel<<<grid, 256, SMEM_DYN>>>((const __half*)pxh);
    }

    // 3) logits = x @ head_w^T via single-pass fp16 mma.sync (2-stage, staged epilogue)
    {
        cudaFuncSetAttribute(mma_gemm_kernel, cudaFuncAttributeMaxDynamicSharedMemorySize, SMEM_DYN);
        dim3 grid(M_ROWS / BM, (V_SIZE + BN - 1) / BN);
        mma_gemm_kernel<<<grid, 256, SMEM_DYN>>>(
            (const __half*)pxh, (const __half*)pwh, logits);
    }

    // 4) fused causal qk^T + copy-scatter into logits
    {
        cudaFuncSetAttribute(qk_scatter_kernel, cudaFuncAttributeMaxDynamicSharedMemorySize, SMEM_DYN);
        qk_scatter_kernel<<<B_SIZE * 36, 256, SMEM_DYN>>>(idx, logits);
    }
}